// round 2
// baseline (speedup 1.0000x reference)
#include <cuda_runtime.h>

#define NN 50000
#define EE 800000
#define DD 512
#define NV4 (DD/4)

// ---------------- static scratch (no allocations allowed) ----------------
__device__ float g_s1[(size_t)NN * DD];
__device__ float g_s2[(size_t)NN * DD];
__device__ float g_m1[(size_t)NN * DD];
__device__ float g_m2[(size_t)NN * DD];
__device__ float g_l1[(size_t)NN * DD];
__device__ float g_l2[(size_t)NN * DD];
__device__ float g_aggs[(size_t)NN * DD];   // segment sum
__device__ float g_aggm[(size_t)NN * DD];   // segment max
__device__ float g_z[(size_t)4 * NN * DD];  // z planes (also reused for cat out in plane 0)
__device__ int   g_deg[NN];
__device__ int   g_rowp[NN + 1];
__device__ int   g_cur[NN];
__device__ int   g_csrc[EE];
__device__ float g_invdeg[NN];
__device__ float g_csum[4 * DD];
__device__ float g_csqr[4 * DD];
__device__ float g_scale[4 * DD];
__device__ float g_shift[4 * DD];

// ---------------- CSR build ----------------
__global__ void k_count(const int* __restrict__ dst, int E) {
    int e = blockIdx.x * blockDim.x + threadIdx.x;
    if (e < E) atomicAdd(&g_deg[dst[e]], 1);
}

__global__ void k_scan(int M) {
    __shared__ int sh[1024];
    __shared__ int running;
    if (threadIdx.x == 0) running = 0;
    __syncthreads();
    for (int base = 0; base < M; base += 1024) {
        int i = base + threadIdx.x;
        int v = (i < M) ? g_deg[i] : 0;
        sh[threadIdx.x] = v;
        __syncthreads();
        for (int off = 1; off < 1024; off <<= 1) {
            int t = 0;
            if ((int)threadIdx.x >= off) t = sh[threadIdx.x - off];
            __syncthreads();
            sh[threadIdx.x] += t;
            __syncthreads();
        }
        int incl = sh[threadIdx.x];
        int excl = running + incl - v;
        if (i < M) {
            g_rowp[i] = excl;
            g_cur[i] = excl;
            g_invdeg[i] = 1.0f / (float)(v > 1 ? v : 1);
        }
        __syncthreads();
        if (threadIdx.x == 0) running += sh[1023];
        __syncthreads();
    }
    if (threadIdx.x == 0) g_rowp[M] = running;
}

__global__ void k_scatter(const int* __restrict__ src, const int* __restrict__ dst, int E) {
    int e = blockIdx.x * blockDim.x + threadIdx.x;
    if (e < E) {
        int d = dst[e];
        int p = atomicAdd(&g_cur[d], 1);
        g_csrc[p] = src[e];
    }
}

// ---------------- aggregation: one block (128 thr) per node ----------------
__global__ void k_aggregate(const float* __restrict__ X) {
    int nid = blockIdx.x;
    int t = threadIdx.x;
    int beg = g_rowp[nid], end = g_rowp[nid + 1];
    float4 s = make_float4(0.f, 0.f, 0.f, 0.f);
    float4 m = make_float4(-3.4e38f, -3.4e38f, -3.4e38f, -3.4e38f);
    const float4* Xb = (const float4*)X;
    for (int e = beg; e < end; e++) {
        int r = __ldg(&g_csrc[e]);
        float4 v = __ldg(Xb + (size_t)r * NV4 + t);
        s.x += v.x; s.y += v.y; s.z += v.z; s.w += v.w;
        m.x = fmaxf(m.x, v.x); m.y = fmaxf(m.y, v.y);
        m.z = fmaxf(m.z, v.z); m.w = fmaxf(m.w, v.w);
    }
    if (beg == end) m = make_float4(0.f, 0.f, 0.f, 0.f);
    ((float4*)g_aggs)[(size_t)nid * NV4 + t] = s;
    ((float4*)g_aggm)[(size_t)nid * NV4 + t] = m;
}

// ---------------- GEMM: z[k] = A_k @ W[k] (+ invdeg rowscale for k==2) + b[k] ----------
__global__ void __launch_bounds__(256, 2)
k_gemm_z(const float* __restrict__ X, const float* __restrict__ W4,
         const float* __restrict__ b4, int M) {
    const int kpl = blockIdx.z;
    const float* A = (kpl == 0) ? X : ((kpl == 3) ? g_aggm : g_aggs);
    const float* Bw = W4 + (size_t)kpl * DD * DD;
    __shared__ float As[8][128];
    __shared__ float Bs[8][128];
    const int tid = threadIdx.x;
    const int rowBase = blockIdx.x * 128;
    const int colBase = blockIdx.y * 128;
    const int aRow = tid >> 1;
    const int aCol = (tid & 1) << 2;
    const int bRow = tid >> 5;
    const int bCol = (tid & 31) << 2;
    const int tx = tid & 15;
    const int ty = tid >> 4;
    float acc[8][8];
#pragma unroll
    for (int i = 0; i < 8; i++)
#pragma unroll
        for (int j = 0; j < 8; j++) acc[i][j] = 0.f;

    const int gr = rowBase + aRow;
    const float* aPtr = A + (size_t)gr * DD + aCol;
    const float* bPtr = Bw + (size_t)bRow * DD + colBase + bCol;
    const bool aOk = (gr < M);

    for (int k0 = 0; k0 < DD; k0 += 8) {
        float4 av = make_float4(0.f, 0.f, 0.f, 0.f);
        if (aOk) av = *(const float4*)(aPtr + k0);
        As[aCol + 0][aRow] = av.x;
        As[aCol + 1][aRow] = av.y;
        As[aCol + 2][aRow] = av.z;
        As[aCol + 3][aRow] = av.w;
        *(float4*)(&Bs[bRow][bCol]) = *(const float4*)(bPtr + (size_t)k0 * DD);
        __syncthreads();
#pragma unroll
        for (int kk = 0; kk < 8; kk++) {
            float ar[8], br[8];
            *(float4*)(ar)     = *(const float4*)&As[kk][ty * 4];
            *(float4*)(ar + 4) = *(const float4*)&As[kk][64 + ty * 4];
            *(float4*)(br)     = *(const float4*)&Bs[kk][tx * 4];
            *(float4*)(br + 4) = *(const float4*)&Bs[kk][64 + tx * 4];
#pragma unroll
            for (int i = 0; i < 8; i++)
#pragma unroll
                for (int j = 0; j < 8; j++)
                    acc[i][j] = fmaf(ar[i], br[j], acc[i][j]);
        }
        __syncthreads();
    }
    // epilogue
    float4 b0 = *(const float4*)&b4[kpl * DD + colBase + tx * 4];
    float4 b1 = *(const float4*)&b4[kpl * DD + colBase + 64 + tx * 4];
#pragma unroll
    for (int i = 0; i < 8; i++) {
        int row = rowBase + ((i < 4) ? (ty * 4 + i) : (64 + ty * 4 + i - 4));
        if (row >= M) continue;
        float rs = (kpl == 2) ? g_invdeg[row] : 1.0f;
        float* zr = g_z + ((size_t)kpl * M + row) * DD;
        float4 v0, v1;
        v0.x = fmaf(acc[i][0], rs, b0.x);
        v0.y = fmaf(acc[i][1], rs, b0.y);
        v0.z = fmaf(acc[i][2], rs, b0.z);
        v0.w = fmaf(acc[i][3], rs, b0.w);
        v1.x = fmaf(acc[i][4], rs, b1.x);
        v1.y = fmaf(acc[i][5], rs, b1.y);
        v1.z = fmaf(acc[i][6], rs, b1.z);
        v1.w = fmaf(acc[i][7], rs, b1.w);
        *(float4*)(zr + colBase + tx * 4) = v0;
        *(float4*)(zr + colBase + 64 + tx * 4) = v1;
    }
}

// ---------------- cat GEMM: z0 = [m1|m2|l1|l2] @ catW + catb ----------------
__global__ void __launch_bounds__(256, 2)
k_gemm_cat(const float* __restrict__ Bw, const float* __restrict__ bias, int M) {
    __shared__ float As[8][128];
    __shared__ float Bs[8][128];
    const int tid = threadIdx.x;
    const int rowBase = blockIdx.x * 128;
    const int colBase = blockIdx.y * 128;
    const int aRow = tid >> 1;
    const int aCol = (tid & 1) << 2;
    const int bRow = tid >> 5;
    const int bCol = (tid & 31) << 2;
    const int tx = tid & 15;
    const int ty = tid >> 4;
    float acc[8][8];
#pragma unroll
    for (int i = 0; i < 8; i++)
#pragma unroll
        for (int j = 0; j < 8; j++) acc[i][j] = 0.f;

    const int gr = rowBase + aRow;
    const bool aOk = (gr < M);

    for (int k0 = 0; k0 < 4 * DD; k0 += 8) {
        int si = k0 >> 9;
        const float* A = (si == 0) ? g_m1 : (si == 1) ? g_m2 : (si == 2) ? g_l1 : g_l2;
        int kin = k0 & (DD - 1);
        float4 av = make_float4(0.f, 0.f, 0.f, 0.f);
        if (aOk) av = *(const float4*)(A + (size_t)gr * DD + kin + aCol);
        As[aCol + 0][aRow] = av.x;
        As[aCol + 1][aRow] = av.y;
        As[aCol + 2][aRow] = av.z;
        As[aCol + 3][aRow] = av.w;
        *(float4*)(&Bs[bRow][bCol]) =
            *(const float4*)(Bw + (size_t)(k0 + bRow) * DD + colBase + bCol);
        __syncthreads();
#pragma unroll
        for (int kk = 0; kk < 8; kk++) {
            float ar[8], br[8];
            *(float4*)(ar)     = *(const float4*)&As[kk][ty * 4];
            *(float4*)(ar + 4) = *(const float4*)&As[kk][64 + ty * 4];
            *(float4*)(br)     = *(const float4*)&Bs[kk][tx * 4];
            *(float4*)(br + 4) = *(const float4*)&Bs[kk][64 + tx * 4];
#pragma unroll
            for (int i = 0; i < 8; i++)
#pragma unroll
                for (int j = 0; j < 8; j++)
                    acc[i][j] = fmaf(ar[i], br[j], acc[i][j]);
        }
        __syncthreads();
    }
    float4 b0 = *(const float4*)&bias[colBase + tx * 4];
    float4 b1 = *(const float4*)&bias[colBase + 64 + tx * 4];
#pragma unroll
    for (int i = 0; i < 8; i++) {
        int row = rowBase + ((i < 4) ? (ty * 4 + i) : (64 + ty * 4 + i - 4));
        if (row >= M) continue;
        float* zr = g_z + (size_t)row * DD;
        float4 v0, v1;
        v0.x = acc[i][0] + b0.x; v0.y = acc[i][1] + b0.y;
        v0.z = acc[i][2] + b0.z; v0.w = acc[i][3] + b0.w;
        v1.x = acc[i][4] + b1.x; v1.y = acc[i][5] + b1.y;
        v1.z = acc[i][6] + b1.z; v1.w = acc[i][7] + b1.w;
        *(float4*)(zr + colBase + tx * 4) = v0;
        *(float4*)(zr + colBase + 64 + tx * 4) = v1;
    }
}

// ---------------- per-(k,d) stats over nodes ----------------
__global__ void k_stats(int M) {
    int k = blockIdx.x >> 2;
    int d = ((blockIdx.x & 3) << 7) + threadIdx.x;
    int rows = (M + gridDim.y - 1) / gridDim.y;
    int r0 = blockIdx.y * rows;
    int r1 = r0 + rows; if (r1 > M) r1 = M;
    const float* p = g_z + ((size_t)k * M) * DD + d;
    float s = 0.f, q = 0.f;
    for (int r = r0; r < r1; r++) {
        float v = __ldg(p + (size_t)r * DD);
        s += v;
        q = fmaf(v, v, q);
    }
    atomicAdd(&g_csum[k * DD + d], s);
    atomicAdd(&g_csqr[k * DD + d], q);
}

__global__ void k_finalize(const float* __restrict__ gam, const float* __restrict__ bet,
                           int M, int P) {
    int i = blockIdx.x * blockDim.x + threadIdx.x;
    if (i < P * DD) {
        float inv = 1.0f / (float)M;
        float mu = g_csum[i] * inv;
        float var = g_csqr[i] * inv - mu * mu;
        float sc = rsqrtf(var + 1e-5f) * gam[i];
        g_scale[i] = sc;
        g_shift[i] = bet[i] - mu * sc;
    }
}

// ---------------- weighted relu combine over k ----------------
__global__ void k_combine(const float* __restrict__ w, float* __restrict__ out,
                          int M, int acc) {
    int idx = blockIdx.x * blockDim.x + threadIdx.x;
    int total = M * NV4;
    if (idx >= total) return;
    int dc = (idx % NV4) * 4;
    float4 r = acc ? ((const float4*)out)[idx] : make_float4(0.f, 0.f, 0.f, 0.f);
#pragma unroll
    for (int k = 0; k < 4; k++) {
        float wk = __ldg(w + k);
        float4 v = __ldg((const float4*)g_z + (size_t)k * M * NV4 + idx);
        float4 sc = *(const float4*)&g_scale[k * DD + dc];
        float4 sh = *(const float4*)&g_shift[k * DD + dc];
        float e;
        e = fmaxf(fmaf(v.x, sc.x, sh.x), 0.f); r.x = fmaf(wk, e, r.x);
        e = fmaxf(fmaf(v.y, sc.y, sh.y), 0.f); r.y = fmaf(wk, e, r.y);
        e = fmaxf(fmaf(v.z, sc.z, sh.z), 0.f); r.z = fmaf(wk, e, r.z);
        e = fmaxf(fmaf(v.w, sc.w, sh.w), 0.f); r.w = fmaf(wk, e, r.w);
    }
    ((float4*)out)[idx] = r;
}

// ---------------- final residual + BN + relu ----------------
__global__ void k_final(const float* __restrict__ h, float* __restrict__ out, int M) {
    int idx = blockIdx.x * blockDim.x + threadIdx.x;
    int total = M * NV4;
    if (idx >= total) return;
    int dc = (idx % NV4) * 4;
    float4 v = ((const float4*)g_z)[idx];
    float4 sc = *(const float4*)&g_scale[dc];
    float4 sh = *(const float4*)&g_shift[dc];
    float4 hv = ((const float4*)h)[idx];
    float4 o;
    o.x = hv.x + fmaxf(fmaf(v.x, sc.x, sh.x), 0.f);
    o.y = hv.y + fmaxf(fmaf(v.y, sc.y, sh.y), 0.f);
    o.z = hv.z + fmaxf(fmaf(v.z, sc.z, sh.z), 0.f);
    o.w = hv.w + fmaxf(fmaf(v.w, sc.w, sh.w), 0.f);
    ((float4*)out)[idx] = o;
}

// ---------------- host orchestration ----------------
static void run_mixed(const float* X, const float* W4, const float* b4,
                      const float* g4, const float* be4, const float* w4,
                      float* outp, int acc, int M, void* sump, void* sqrp) {
    cudaMemsetAsync(sump, 0, 4 * DD * sizeof(float));
    cudaMemsetAsync(sqrp, 0, 4 * DD * sizeof(float));
    dim3 gg((M + 127) / 128, 4, 4);
    k_gemm_z<<<gg, 256>>>(X, W4, b4, M);
    k_stats<<<dim3(16, 128), 128>>>(M);
    k_finalize<<<8, 256>>>(g4, be4, M, 4);
    k_combine<<<(M * NV4 + 255) / 256, 256>>>(w4, outp, M, acc);
}

extern "C" void kernel_launch(void* const* d_in, const int* in_sizes, int n_in,
                              void* d_out, int out_size) {
    const float* h    = (const float*)d_in[0];
    const int*   src  = (const int*)d_in[1];
    const int*   dst  = (const int*)d_in[2];
    const float* wf   = (const float*)d_in[3];
    const float* wm   = (const float*)d_in[4];
    const float* wl   = (const float*)d_in[5];
    const float* pfW  = (const float*)d_in[6];
    const float* pfb  = (const float*)d_in[7];
    const float* pfg  = (const float*)d_in[8];
    const float* pfB  = (const float*)d_in[9];
    const float* pmW  = (const float*)d_in[10];
    const float* pmb  = (const float*)d_in[11];
    const float* pmg  = (const float*)d_in[12];
    const float* pmB  = (const float*)d_in[13];
    const float* plW  = (const float*)d_in[14];
    const float* plb  = (const float*)d_in[15];
    const float* plg  = (const float*)d_in[16];
    const float* plB  = (const float*)d_in[17];
    const float* catW = (const float*)d_in[18];
    const float* catb = (const float*)d_in[19];
    const float* bng  = (const float*)d_in[20];
    const float* bnb  = (const float*)d_in[21];

    int M = in_sizes[0] / DD;
    int E = in_sizes[1];
    float* out = (float*)d_out;

    void *s1, *s2, *m1, *m2, *l1, *l2, *degp, *sump, *sqrp;
    cudaGetSymbolAddress(&s1, g_s1);
    cudaGetSymbolAddress(&s2, g_s2);
    cudaGetSymbolAddress(&m1, g_m1);
    cudaGetSymbolAddress(&m2, g_m2);
    cudaGetSymbolAddress(&l1, g_l1);
    cudaGetSymbolAddress(&l2, g_l2);
    cudaGetSymbolAddress(&degp, g_deg);
    cudaGetSymbolAddress(&sump, g_csum);
    cudaGetSymbolAddress(&sqrp, g_csqr);

    const size_t slabW = (size_t)4 * DD * DD;  // per-layer weight slab (4,D,D)
    const size_t slabB = 4 * DD;               // per-layer (4,D)

    // CSR build (shared by all aggregations this launch)
    cudaMemsetAsync(degp, 0, M * sizeof(int));
    k_count<<<(E + 255) / 256, 256>>>(dst, E);
    k_scan<<<1, 1024>>>(M);
    k_scatter<<<(E + 255) / 256, 256>>>(src, dst, E);

    // first block: s1 = mixed(wf0, h); s2 = mixed(wf1, h) + mixed(wf2, s1)
    k_aggregate<<<M, 128>>>(h);
    run_mixed(h, pfW + 0 * slabW, pfb + 0 * slabB, pfg + 0 * slabB, pfB + 0 * slabB,
              wf + 0, (float*)s1, 0, M, sump, sqrp);
    run_mixed(h, pfW + 1 * slabW, pfb + 1 * slabB, pfg + 1 * slabB, pfB + 1 * slabB,
              wf + 4, (float*)s2, 0, M, sump, sqrp);
    k_aggregate<<<M, 128>>>((const float*)s1);
    run_mixed((const float*)s1, pfW + 2 * slabW, pfb + 2 * slabB, pfg + 2 * slabB,
              pfB + 2 * slabB, wf + 8, (float*)s2, 1, M, sump, sqrp);
    // middle (agg(s1) still valid): m1 = mixed(wm0, s1)
    run_mixed((const float*)s1, pmW + 0 * slabW, pmb + 0 * slabB, pmg + 0 * slabB,
              pmB + 0 * slabB, wm + 0, (float*)m1, 0, M, sump, sqrp);
    k_aggregate<<<M, 128>>>((const float*)s2);
    run_mixed((const float*)s2, pmW + 1 * slabW, pmb + 1 * slabB, pmg + 1 * slabB,
              pmB + 1 * slabB, wm + 4, (float*)m2, 0, M, sump, sqrp);
    // last block: l1 = mixed(wl0,m1)+mixed(wl1,m2); l2 = mixed(wl2,m1)+mixed(wl3,m2)+mixed(wl4,l1)
    k_aggregate<<<M, 128>>>((const float*)m1);
    run_mixed((const float*)m1, plW + 0 * slabW, plb + 0 * slabB, plg + 0 * slabB,
              plB + 0 * slabB, wl + 0, (float*)l1, 0, M, sump, sqrp);
    run_mixed((const float*)m1, plW + 2 * slabW, plb + 2 * slabB, plg + 2 * slabB,
              plB + 2 * slabB, wl + 8, (float*)l2, 0, M, sump, sqrp);
    k_aggregate<<<M, 128>>>((const float*)m2);
    run_mixed((const float*)m2, plW + 1 * slabW, plb + 1 * slabB, plg + 1 * slabB,
              plB + 1 * slabB, wl + 4, (float*)l1, 1, M, sump, sqrp);
    run_mixed((const float*)m2, plW + 3 * slabW, plb + 3 * slabB, plg + 3 * slabB,
              plB + 3 * slabB, wl + 12, (float*)l2, 1, M, sump, sqrp);
    k_aggregate<<<M, 128>>>((const float*)l1);
    run_mixed((const float*)l1, plW + 4 * slabW, plb + 4 * slabB, plg + 4 * slabB,
              plB + 4 * slabB, wl + 16, (float*)l2, 1, M, sump, sqrp);

    // cat GEMM + batchnorm + relu + residual
    k_gemm_cat<<<dim3((M + 127) / 128, 4, 1), 256>>>(catW, catb, M);
    cudaMemsetAsync(sump, 0, 4 * DD * sizeof(float));
    cudaMemsetAsync(sqrp, 0, 4 * DD * sizeof(float));
    k_stats<<<dim3(4, 128), 128>>>(M);
    k_finalize<<<8, 256>>>(bng, bnb, M, 1);
    k_final<<<(M * NV4 + 255) / 256, 256>>>(h, out, M);
}